// round 15
// baseline (speedup 1.0000x reference)
#include <cuda_runtime.h>
#include <cuda_fp16.h>
#include <cstdint>

#define NN 100000
#define EE 800000
#define HEADS 8
#define CH 16
#define DIM 128
#define NEG_SLOPE 0.2f

#define NN2 (2 * NN)
#define SCAN_CHUNK 2048
#define NB_SCAN ((NN2 + SCAN_CHUNK - 1) / SCAN_CHUNK)   // 98

// ---------------- scratch (device globals) --------------------------------------
__device__ __half g_h_in_h[NN * DIM];
__device__ __half g_h_out_h[NN * DIM];
__device__ __half g_W_h[2][DIM * DIM];     // fp16 copies of W_in / W_out
__device__ float  g_asrc_in[NN * HEADS];
__device__ float  g_adst_in[NN * HEADS];
__device__ float  g_asrc_out[NN * HEADS];
__device__ float  g_adst_out[NN * HEADS];

__device__ int      g_cnt[NN2];
__device__ int      g_off[NN2 + 1];
__device__ int      g_rank[2 * EE];        // per-edge rank within its node
__device__ unsigned g_desc[NB_SCAN];       // lookback descriptors
__device__ int      g_nbr[2 * EE];

// ---------------- helpers ------------------------------------------------------
__device__ __forceinline__ float lrelu(float v) {
    return v > 0.0f ? v : NEG_SLOPE * v;
}

__device__ __forceinline__ void ldsm_x4(uint32_t addr, uint32_t& r0, uint32_t& r1,
                                        uint32_t& r2, uint32_t& r3) {
    asm volatile("ldmatrix.sync.aligned.m8n8.x4.shared.b16 {%0,%1,%2,%3}, [%4];"
                 : "=r"(r0), "=r"(r1), "=r"(r2), "=r"(r3) : "r"(addr));
}
__device__ __forceinline__ void ldsm_x4_t(uint32_t addr, uint32_t& r0, uint32_t& r1,
                                          uint32_t& r2, uint32_t& r3) {
    asm volatile("ldmatrix.sync.aligned.m8n8.x4.trans.shared.b16 {%0,%1,%2,%3}, [%4];"
                 : "=r"(r0), "=r"(r1), "=r"(r2), "=r"(r3) : "r"(addr));
}
__device__ __forceinline__ void mma16816(float* c, const uint32_t* a, const uint32_t* b) {
    asm volatile(
        "mma.sync.aligned.m16n8k16.row.col.f32.f16.f16.f32 "
        "{%0,%1,%2,%3},{%4,%5,%6,%7},{%8,%9},{%10,%11,%12,%13};"
        : "=f"(c[0]), "=f"(c[1]), "=f"(c[2]), "=f"(c[3])
        : "r"(a[0]), "r"(a[1]), "r"(a[2]), "r"(a[3]), "r"(b[0]), "r"(b[1]),
          "f"(c[0]), "f"(c[1]), "f"(c[2]), "f"(c[3]));
}

// ---------------- weight conversion (once per launch) ---------------------------
__global__ void wconv_kernel(const float* __restrict__ Win,
                             const float* __restrict__ Wout) {
    int t = blockIdx.x * blockDim.x + threadIdx.x;
    if (t >= 2 * DIM * DIM / 4) return;
    int m = t / (DIM * DIM / 4);
    int i = t % (DIM * DIM / 4);
    const float* W = m ? Wout : Win;
    float4 v = *(const float4*)&W[i * 4];
    __half2 h0 = __floats2half2_rn(v.x, v.y);
    __half2 h1 = __floats2half2_rn(v.z, v.w);
    *(uint2*)&g_W_h[m][i * 4] = make_uint2(*(unsigned*)&h0, *(unsigned*)&h1);
}

// ---------------- CSR build ----------------------------------------------------
__global__ void zero_cnt_kernel() {
    int t = blockIdx.x * blockDim.x + threadIdx.x;
    if (t < NN2) g_cnt[t] = 0;
    if (t < NB_SCAN) g_desc[t] = 0u;
}

// hist also records each edge's rank within its node (atomicAdd return value)
__global__ void hist_kernel(const int* __restrict__ ei) {
    int e = blockIdx.x * blockDim.x + threadIdx.x;
    if (e >= EE) return;
    int s = __ldg(&ei[e]);
    int d = __ldg(&ei[EE + e]);
    int r0 = atomicAdd(&g_cnt[d], 1);
    int r1 = atomicAdd(&g_cnt[NN + s], 1);
    g_rank[e] = r0;
    g_rank[EE + e] = r1;
}

// single-kernel exclusive scan with decoupled lookback (98 blocks, all resident)
__global__ void scan_fused_kernel() {
    __shared__ int sh[256];
    __shared__ int s_prefix;
    unsigned FULL = 0xFFFFFFFFu;
    int b = blockIdx.x;
    int t = threadIdx.x;
    int base = b * SCAN_CHUNK + t * 8;

    int v[8];
    int s = 0;
#pragma unroll
    for (int k = 0; k < 8; k++) {
        int idx = base + k;
        v[k] = (idx < NN2) ? g_cnt[idx] : 0;
        s += v[k];
    }
    sh[t] = s;
    __syncthreads();
#pragma unroll
    for (int off = 1; off < 256; off <<= 1) {
        int x = (t >= off) ? sh[t - off] : 0;
        __syncthreads();
        if (t >= off) sh[t] += x;
        __syncthreads();
    }
    int excl = sh[t] - s;
    int total = sh[255];

    if (t == 0) atomicExch(&g_desc[b], (1u << 30) | (unsigned)total);

    if (t < 32) {
        int lane = t;
        int prefix = 0;
        int i = b - 1;
        while (i >= 0) {
            int idx = i - lane;
            unsigned status;
            int val;
            if (idx >= 0) {
                unsigned d;
                do { d = *(volatile unsigned*)&g_desc[idx]; } while (d == 0u);
                status = d >> 30;
                val = (int)(d & 0x3FFFFFFFu);
            } else {
                status = 2u;
                val = 0;
            }
            unsigned pm = __ballot_sync(FULL, status == 2u);
            int firstP = __ffs(pm) - 1;
            int contrib;
            if (pm) contrib = (lane <= firstP) ? val : 0;
            else    contrib = val;
#pragma unroll
            for (int o = 16; o; o >>= 1)
                contrib += __shfl_xor_sync(FULL, contrib, o);
            prefix += contrib;
            if (pm) break;
            i -= 32;
        }
        if (lane == 0) {
            s_prefix = prefix;
            atomicExch(&g_desc[b], (2u << 30) | (unsigned)(prefix + total));
        }
    }
    __syncthreads();

    int run = s_prefix + excl;
#pragma unroll
    for (int k = 0; k < 8; k++) {
        int idx = base + k;
        if (idx < NN2) g_off[idx] = run;
        run += v[k];
    }
    if (b == 0 && t == 0) g_off[NN2] = 2 * EE;
}

// atomic-free scatter: position = offset + precomputed rank
__global__ void scatter_kernel(const int* __restrict__ ei) {
    int e = blockIdx.x * blockDim.x + threadIdx.x;
    if (e >= EE) return;
    int s = __ldg(&ei[e]);
    int d = __ldg(&ei[EE + e]);
    g_nbr[__ldg(&g_off[d]) + g_rank[e]] = s;
    g_nbr[__ldg(&g_off[NN + s]) + g_rank[EE + e]] = d;
}

// ---------------- fused projection GEMM + alpha epilogue ------------------------
__device__ __forceinline__ void mma_tile(uint32_t baseA, uint32_t baseB, int kOff,
                                         int m0, int n0, int lane,
                                         float c[2][8][4]) {
#pragma unroll
    for (int ks = 0; ks < 4; ks++) {
        uint32_t a[2][4];
#pragma unroll
        for (int mi = 0; mi < 2; mi++) {
            int row = m0 + mi * 16 + (lane & 15);
            int chunk = ks * 2 + (lane >> 4);
            int swz = chunk ^ (row & 7);
            ldsm_x4(baseA + row * 128 + swz * 16,
                    a[mi][0], a[mi][1], a[mi][2], a[mi][3]);
        }
        uint32_t b[4][4];
#pragma unroll
        for (int np = 0; np < 4; np++) {
            int row = kOff + ks * 16 + (lane & 15);
            int chunk = (n0 >> 3) + np * 2 + (lane >> 4);
            int swz = chunk ^ (row & 7);
            ldsm_x4_t(baseB + row * 256 + swz * 16,
                      b[np][0], b[np][1], b[np][2], b[np][3]);
        }
#pragma unroll
        for (int mi = 0; mi < 2; mi++)
#pragma unroll
            for (int ni = 0; ni < 8; ni++)
                mma16816(c[mi][ni], a[mi], &b[ni >> 1][(ni & 1) * 2]);
    }
}

__global__ __launch_bounds__(512)
void gemm_fused_kernel(const float* __restrict__ A,
                       const float* __restrict__ asi, const float* __restrict__ adi,
                       const float* __restrict__ aso, const float* __restrict__ ado,
                       int M) {
    extern __shared__ __align__(16) char dynsmem[];
    char* sW = dynsmem;                 // [mat][128 rows x 256 B]  = 64 KB
    char* sA = dynsmem + 65536;         // [buf][128 rows x 128 B]  = 32 KB

    int t = threadIdx.x;
    int w = t >> 5;
    int lane = t & 31;
    int mat = w >> 3;
    int w8 = w & 7;
    int m0 = (w8 >> 1) * 32;
    int n0 = (w8 & 1) * 64;
    int row0 = blockIdx.x * 128;

    uint32_t baseW = (uint32_t)__cvta_generic_to_shared(sW) + mat * 32768;
    uint32_t baseA0 = (uint32_t)__cvta_generic_to_shared(sA);
    uint32_t baseA1 = baseA0 + 16384;

    float c[2][8][4];
#pragma unroll
    for (int mi = 0; mi < 2; mi++)
#pragma unroll
        for (int ni = 0; ni < 8; ni++)
#pragma unroll
            for (int q = 0; q < 4; q++) c[mi][ni][q] = 0.f;

#pragma unroll
    for (int i = 0; i < 16; i++) {
        int idx = i * 512 + t;
        int m = idx >> 12;
        int r = (idx >> 5) & 127;
        int c4 = idx & 31;
        uint2 v = *(const uint2*)&g_W_h[m][r * DIM + c4 * 4];
        int swz = (c4 >> 1) ^ (r & 7);
        *(uint2*)(sW + m * 32768 + r * 256 + swz * 16 + (c4 & 1) * 8) = v;
    }
#pragma unroll
    for (int i = 0; i < 4; i++) {
        int idx = i * 512 + t;
        int row = idx >> 4;
        int c4 = idx & 15;
        float4 v = make_float4(0.f, 0.f, 0.f, 0.f);
        if (row0 + row < M)
            v = *(const float4*)&A[(size_t)(row0 + row) * DIM + c4 * 4];
        __half2 h0 = __floats2half2_rn(v.x, v.y);
        __half2 h1 = __floats2half2_rn(v.z, v.w);
        int swz = (c4 >> 1) ^ (row & 7);
        *(uint2*)(sA + row * 128 + swz * 16 + (c4 & 1) * 8) =
            make_uint2(*(unsigned*)&h0, *(unsigned*)&h1);
    }
    __syncthreads();

    float4 ra[4];
#pragma unroll
    for (int i = 0; i < 4; i++) {
        int idx = i * 512 + t;
        int row = idx >> 4;
        int c4 = idx & 15;
        ra[i] = make_float4(0.f, 0.f, 0.f, 0.f);
        if (row0 + row < M)
            ra[i] = *(const float4*)&A[(size_t)(row0 + row) * DIM + 64 + c4 * 4];
    }

    mma_tile(baseA0, baseW, 0, m0, n0, lane, c);

#pragma unroll
    for (int i = 0; i < 4; i++) {
        int idx = i * 512 + t;
        int row = idx >> 4;
        int c4 = idx & 15;
        __half2 h0 = __floats2half2_rn(ra[i].x, ra[i].y);
        __half2 h1 = __floats2half2_rn(ra[i].z, ra[i].w);
        int swz = (c4 >> 1) ^ (row & 7);
        *(uint2*)(sA + 16384 + row * 128 + swz * 16 + (c4 & 1) * 8) =
            make_uint2(*(unsigned*)&h0, *(unsigned*)&h1);
    }
    __syncthreads();

    mma_tile(baseA1, baseW, 64, m0, n0, lane, c);

    // ---- epilogue 1: fp16 h stores ----
    __half* Ch = mat ? g_h_out_h : g_h_in_h;
    int gid = lane >> 2;
    int qq = lane & 3;
#pragma unroll
    for (int mi = 0; mi < 2; mi++) {
#pragma unroll
        for (int ni = 0; ni < 8; ni++) {
            int row = row0 + m0 + mi * 16 + gid;
            int col = n0 + ni * 8 + qq * 2;
            if (row < M) {
                __half2 hv = __floats2half2_rn(c[mi][ni][0], c[mi][ni][1]);
                *(__half2*)&Ch[(size_t)row * DIM + col] = hv;
            }
            if (row + 8 < M) {
                __half2 hv = __floats2half2_rn(c[mi][ni][2], c[mi][ni][3]);
                *(__half2*)&Ch[(size_t)(row + 8) * DIM + col] = hv;
            }
        }
    }

    // ---- epilogue 2: alpha logits ----
    const float* av_s = mat ? aso : asi;
    const float* av_d = mat ? ado : adi;
    float* p_src = mat ? g_asrc_out : g_asrc_in;
    float* p_dst = mat ? g_adst_out : g_adst_in;
    int hb = (w8 & 1) * 4;

#pragma unroll
    for (int mi = 0; mi < 2; mi++) {
        float ps[2][4], pd[2][4];
#pragma unroll
        for (int r = 0; r < 2; r++)
#pragma unroll
            for (int hl = 0; hl < 4; hl++) { ps[r][hl] = 0.f; pd[r][hl] = 0.f; }
#pragma unroll
        for (int ni = 0; ni < 8; ni++) {
            int col = n0 + ni * 8 + qq * 2;
            float s0 = __ldg(&av_s[col]), s1 = __ldg(&av_s[col + 1]);
            float d0 = __ldg(&av_d[col]), d1 = __ldg(&av_d[col + 1]);
            int hl = ni >> 1;
            ps[0][hl] += c[mi][ni][0] * s0 + c[mi][ni][1] * s1;
            ps[1][hl] += c[mi][ni][2] * s0 + c[mi][ni][3] * s1;
            pd[0][hl] += c[mi][ni][0] * d0 + c[mi][ni][1] * d1;
            pd[1][hl] += c[mi][ni][2] * d0 + c[mi][ni][3] * d1;
        }
#pragma unroll
        for (int r = 0; r < 2; r++)
#pragma unroll
            for (int hl = 0; hl < 4; hl++) {
                ps[r][hl] += __shfl_xor_sync(0xFFFFFFFFu, ps[r][hl], 1);
                ps[r][hl] += __shfl_xor_sync(0xFFFFFFFFu, ps[r][hl], 2);
                pd[r][hl] += __shfl_xor_sync(0xFFFFFFFFu, pd[r][hl], 1);
                pd[r][hl] += __shfl_xor_sync(0xFFFFFFFFu, pd[r][hl], 2);
            }
        if (qq == 0) {
#pragma unroll
            for (int r = 0; r < 2; r++) {
                int row = row0 + m0 + mi * 16 + gid + r * 8;
                if (row < M) {
                    *(float4*)&p_src[row * HEADS + hb] =
                        make_float4(ps[r][0], ps[r][1], ps[r][2], ps[r][3]);
                    *(float4*)&p_dst[row * HEADS + hb] =
                        make_float4(pd[r][0], pd[r][1], pd[r][2], pd[r][3]);
                }
            }
        }
    }
}

// ---------------- aggregation: warp per node, both directions interleaved -------
// Up to 4 independent edge chains in flight (2 per direction).
__global__ __launch_bounds__(256)
void agg_kernel(float* __restrict__ out,
                const float* __restrict__ b_in,
                const float* __restrict__ b_out) {
    int w = (blockIdx.x * blockDim.x + threadIdx.x) >> 5;
    if (w >= NN) return;
    int n = w;
    int lane = threadIdx.x & 31;
    int c4 = lane * 4;
    int hd = lane >> 2;

    float4 bi = *(const float4*)&b_in[c4];
    float4 bo = *(const float4*)&b_out[c4];
    float o0 = bi.x + bo.x, o1 = bi.y + bo.y;
    float o2 = bi.z + bo.z, o3 = bi.w + bo.w;

    int base0 = g_off[n];
    int deg0  = g_off[n + 1] - base0;
    int base1 = g_off[NN + n];
    int deg1  = g_off[NN + n + 1] - base1;
    float ad0 = __ldg(&g_adst_in[n * HEADS + hd]);
    float ad1 = __ldg(&g_adst_out[n * HEADS + hd]);

    float den0 = 0.f, den1 = 0.f;
    float x0 = 0.f, x1 = 0.f, x2 = 0.f, x3 = 0.f;   // in-dir accum
    float y0 = 0.f, y1 = 0.f, y2 = 0.f, y3 = 0.f;   // out-dir accum

    int degm = deg0 > deg1 ? deg0 : deg1;
    for (int j = 0; j < degm; j += 2) {
        bool aA = j < deg0, aB = j + 1 < deg0;
        bool aC = j < deg1, aD = j + 1 < deg1;

        // index loads (independent)
        int sA = aA ? __ldg(&g_nbr[base0 + j])     : 0;
        int sB = aB ? __ldg(&g_nbr[base0 + j + 1]) : 0;
        int sC = aC ? __ldg(&g_nbr[base1 + j])     : 0;
        int sD = aD ? __ldg(&g_nbr[base1 + j + 1]) : 0;

        // alpha + h loads (4 independent chains)
        float alA = aA ? __ldg(&g_asrc_in[sA * HEADS + hd]) : 0.f;
        float alB = aB ? __ldg(&g_asrc_in[sB * HEADS + hd]) : 0.f;
        float alC = aC ? __ldg(&g_asrc_out[sC * HEADS + hd]) : 0.f;
        float alD = aD ? __ldg(&g_asrc_out[sD * HEADS + hd]) : 0.f;
        uint2 vA = make_uint2(0u, 0u), vB = make_uint2(0u, 0u);
        uint2 vC = make_uint2(0u, 0u), vD = make_uint2(0u, 0u);
        if (aA) vA = *(const uint2*)&g_h_in_h[(size_t)sA * DIM + c4];
        if (aB) vB = *(const uint2*)&g_h_in_h[(size_t)sB * DIM + c4];
        if (aC) vC = *(const uint2*)&g_h_out_h[(size_t)sC * DIM + c4];
        if (aD) vD = *(const uint2*)&g_h_out_h[(size_t)sD * DIM + c4];

        float pA = aA ? __expf(lrelu(alA + ad0)) : 0.f;
        float pB = aB ? __expf(lrelu(alB + ad0)) : 0.f;
        float pC = aC ? __expf(lrelu(alC + ad1)) : 0.f;
        float pD = aD ? __expf(lrelu(alD + ad1)) : 0.f;

        float2 eA0 = __half22float2(*reinterpret_cast<__half2*>(&vA.x));
        float2 eA1 = __half22float2(*reinterpret_cast<__half2*>(&vA.y));
        float2 eB0 = __half22float2(*reinterpret_cast<__half2*>(&vB.x));
        float2 eB1 = __half22float2(*reinterpret_cast<__half2*>(&vB.y));
        float2 eC0 = __half22float2(*reinterpret_cast<__half2*>(&vC.x));
        float2 eC1 = __half22float2(*reinterpret_cast<__half2*>(&vC.y));
        float2 eD0 = __half22float2(*reinterpret_cast<__half2*>(&vD.x));
        float2 eD1 = __half22float2(*reinterpret_cast<__half2*>(&vD.y));

        den0 += pA + pB;
        den1 += pC + pD;
        x0 += pA * eA0.x + pB * eB0.x;
        x1 += pA * eA0.y + pB * eB0.y;
        x2 += pA * eA1.x + pB * eB1.x;
        x3 += pA * eA1.y + pB * eB1.y;
        y0 += pC * eC0.x + pD * eD0.x;
        y1 += pC * eC0.y + pD * eD0.y;
        y2 += pC * eC1.x + pD * eD1.x;
        y3 += pC * eC1.y + pD * eD1.y;
    }

    float r0 = (deg0 > 0) ? __frcp_rn(den0) : 0.f;
    float r1 = (deg1 > 0) ? __frcp_rn(den1) : 0.f;
    o0 += x0 * r0 + y0 * r1;
    o1 += x1 * r0 + y1 * r1;
    o2 += x2 * r0 + y2 * r1;
    o3 += x3 * r0 + y3 * r1;

    *(float4*)&out[(size_t)n * DIM + c4] = make_float4(o0, o1, o2, o3);
}

// ---------------- launch --------------------------------------------------------
extern "C" void kernel_launch(void* const* d_in, const int* in_sizes, int n_in,
                              void* d_out, int out_size) {
    const float* x        = (const float*)d_in[0];
    const int*   ei       = (const int*)d_in[1];
    const float* W_in     = (const float*)d_in[2];
    const float* a_src_in = (const float*)d_in[3];
    const float* a_dst_in = (const float*)d_in[4];
    const float* b_in     = (const float*)d_in[5];
    const float* W_out    = (const float*)d_in[6];
    const float* a_src_out= (const float*)d_in[7];
    const float* a_dst_out= (const float*)d_in[8];
    const float* b_out    = (const float*)d_in[9];
    float* out = (float*)d_out;

    const int GEMM_SMEM = 65536 + 32768;   // 96 KB dynamic
    cudaFuncSetAttribute(gemm_fused_kernel,
                         cudaFuncAttributeMaxDynamicSharedMemorySize, GEMM_SMEM);

    static cudaStream_t s_side = nullptr;
    static cudaEvent_t ev_fork = nullptr, ev_join = nullptr;
    if (s_side == nullptr) {
        cudaStreamCreateWithFlags(&s_side, cudaStreamNonBlocking);
        cudaEventCreateWithFlags(&ev_fork, cudaEventDisableTiming);
        cudaEventCreateWithFlags(&ev_join, cudaEventDisableTiming);
    }

    // fork: CSR chain on side stream; wconv + GEMM on main stream
    cudaEventRecord(ev_fork, 0);
    cudaStreamWaitEvent(s_side, ev_fork, 0);

    zero_cnt_kernel<<<(NN2 + 255) / 256, 256, 0, s_side>>>();
    hist_kernel<<<(EE + 255) / 256, 256, 0, s_side>>>(ei);
    scan_fused_kernel<<<NB_SCAN, 256, 0, s_side>>>();
    scatter_kernel<<<(EE + 255) / 256, 256, 0, s_side>>>(ei);
    cudaEventRecord(ev_join, s_side);

    wconv_kernel<<<(2 * DIM * DIM / 4 + 255) / 256, 256>>>(W_in, W_out);
    gemm_fused_kernel<<<(NN + 127) / 128, 512, GEMM_SMEM>>>(
        x, a_src_in, a_dst_in, a_src_out, a_dst_out, NN);

    // join, then aggregate
    cudaStreamWaitEvent(0, ev_join, 0);
    agg_kernel<<<(NN * 32 + 255) / 256, 256>>>(out, b_in, b_out);
}

// round 16
// speedup vs baseline: 1.1949x; 1.1949x over previous
#include <cuda_runtime.h>
#include <cuda_fp16.h>
#include <cstdint>

#define NN 100000
#define EE 800000
#define HEADS 8
#define CH 16
#define DIM 128
#define NEG_SLOPE 0.2f

#define NN2 (2 * NN)
#define SCAN_CHUNK 2048
#define NB_SCAN ((NN2 + SCAN_CHUNK - 1) / SCAN_CHUNK)   // 98

// ---------------- scratch (device globals) --------------------------------------
__device__ __half g_h_in_h[NN * DIM];
__device__ __half g_h_out_h[NN * DIM];
__device__ __half g_W_h[2][DIM * DIM];     // fp16 copies of W_in / W_out
__device__ float  g_asrc_in[NN * HEADS];
__device__ float  g_adst_in[NN * HEADS];
__device__ float  g_asrc_out[NN * HEADS];
__device__ float  g_adst_out[NN * HEADS];

__device__ int      g_cnt[NN2];
__device__ int      g_off[NN2 + 1];
__device__ int      g_rank[2 * EE];        // per-edge rank within its node
__device__ unsigned g_desc[NB_SCAN];       // lookback descriptors
__device__ int      g_nbr[2 * EE];

// ---------------- helpers ------------------------------------------------------
__device__ __forceinline__ float lrelu(float v) {
    return v > 0.0f ? v : NEG_SLOPE * v;
}

__device__ __forceinline__ void ldsm_x4(uint32_t addr, uint32_t& r0, uint32_t& r1,
                                        uint32_t& r2, uint32_t& r3) {
    asm volatile("ldmatrix.sync.aligned.m8n8.x4.shared.b16 {%0,%1,%2,%3}, [%4];"
                 : "=r"(r0), "=r"(r1), "=r"(r2), "=r"(r3) : "r"(addr));
}
__device__ __forceinline__ void ldsm_x4_t(uint32_t addr, uint32_t& r0, uint32_t& r1,
                                          uint32_t& r2, uint32_t& r3) {
    asm volatile("ldmatrix.sync.aligned.m8n8.x4.trans.shared.b16 {%0,%1,%2,%3}, [%4];"
                 : "=r"(r0), "=r"(r1), "=r"(r2), "=r"(r3) : "r"(addr));
}
__device__ __forceinline__ void mma16816(float* c, const uint32_t* a, const uint32_t* b) {
    asm volatile(
        "mma.sync.aligned.m16n8k16.row.col.f32.f16.f16.f32 "
        "{%0,%1,%2,%3},{%4,%5,%6,%7},{%8,%9},{%10,%11,%12,%13};"
        : "=f"(c[0]), "=f"(c[1]), "=f"(c[2]), "=f"(c[3])
        : "r"(a[0]), "r"(a[1]), "r"(a[2]), "r"(a[3]), "r"(b[0]), "r"(b[1]),
          "f"(c[0]), "f"(c[1]), "f"(c[2]), "f"(c[3]));
}

// ---------------- weight conversion (once per launch) ---------------------------
__global__ void wconv_kernel(const float* __restrict__ Win,
                             const float* __restrict__ Wout) {
    int t = blockIdx.x * blockDim.x + threadIdx.x;
    if (t >= 2 * DIM * DIM / 4) return;
    int m = t / (DIM * DIM / 4);
    int i = t % (DIM * DIM / 4);
    const float* W = m ? Wout : Win;
    float4 v = *(const float4*)&W[i * 4];
    __half2 h0 = __floats2half2_rn(v.x, v.y);
    __half2 h1 = __floats2half2_rn(v.z, v.w);
    *(uint2*)&g_W_h[m][i * 4] = make_uint2(*(unsigned*)&h0, *(unsigned*)&h1);
}

// ---------------- CSR build ----------------------------------------------------
__global__ void zero_cnt_kernel() {
    int t = blockIdx.x * blockDim.x + threadIdx.x;
    if (t < NN2) g_cnt[t] = 0;
    if (t < NB_SCAN) g_desc[t] = 0u;
}

// hist also records each edge's rank within its node (atomicAdd return value)
__global__ void hist_kernel(const int* __restrict__ ei) {
    int e = blockIdx.x * blockDim.x + threadIdx.x;
    if (e >= EE) return;
    int s = __ldg(&ei[e]);
    int d = __ldg(&ei[EE + e]);
    int r0 = atomicAdd(&g_cnt[d], 1);
    int r1 = atomicAdd(&g_cnt[NN + s], 1);
    g_rank[e] = r0;
    g_rank[EE + e] = r1;
}

// single-kernel exclusive scan with decoupled lookback (98 blocks, all resident)
__global__ void scan_fused_kernel() {
    __shared__ int sh[256];
    __shared__ int s_prefix;
    unsigned FULL = 0xFFFFFFFFu;
    int b = blockIdx.x;
    int t = threadIdx.x;
    int base = b * SCAN_CHUNK + t * 8;

    int v[8];
    int s = 0;
#pragma unroll
    for (int k = 0; k < 8; k++) {
        int idx = base + k;
        v[k] = (idx < NN2) ? g_cnt[idx] : 0;
        s += v[k];
    }
    sh[t] = s;
    __syncthreads();
#pragma unroll
    for (int off = 1; off < 256; off <<= 1) {
        int x = (t >= off) ? sh[t - off] : 0;
        __syncthreads();
        if (t >= off) sh[t] += x;
        __syncthreads();
    }
    int excl = sh[t] - s;
    int total = sh[255];

    if (t == 0) atomicExch(&g_desc[b], (1u << 30) | (unsigned)total);

    if (t < 32) {
        int lane = t;
        int prefix = 0;
        int i = b - 1;
        while (i >= 0) {
            int idx = i - lane;
            unsigned status;
            int val;
            if (idx >= 0) {
                unsigned d;
                do { d = *(volatile unsigned*)&g_desc[idx]; } while (d == 0u);
                status = d >> 30;
                val = (int)(d & 0x3FFFFFFFu);
            } else {
                status = 2u;
                val = 0;
            }
            unsigned pm = __ballot_sync(FULL, status == 2u);
            int firstP = __ffs(pm) - 1;
            int contrib;
            if (pm) contrib = (lane <= firstP) ? val : 0;
            else    contrib = val;
#pragma unroll
            for (int o = 16; o; o >>= 1)
                contrib += __shfl_xor_sync(FULL, contrib, o);
            prefix += contrib;
            if (pm) break;
            i -= 32;
        }
        if (lane == 0) {
            s_prefix = prefix;
            atomicExch(&g_desc[b], (2u << 30) | (unsigned)(prefix + total));
        }
    }
    __syncthreads();

    int run = s_prefix + excl;
#pragma unroll
    for (int k = 0; k < 8; k++) {
        int idx = base + k;
        if (idx < NN2) g_off[idx] = run;
        run += v[k];
    }
    if (b == 0 && t == 0) g_off[NN2] = 2 * EE;
}

// atomic-free scatter: position = offset + precomputed rank
__global__ void scatter_kernel(const int* __restrict__ ei) {
    int e = blockIdx.x * blockDim.x + threadIdx.x;
    if (e >= EE) return;
    int s = __ldg(&ei[e]);
    int d = __ldg(&ei[EE + e]);
    g_nbr[__ldg(&g_off[d]) + g_rank[e]] = s;
    g_nbr[__ldg(&g_off[NN + s]) + g_rank[EE + e]] = d;
}

// ---------------- fused projection GEMM + alpha epilogue ------------------------
__device__ __forceinline__ void mma_tile(uint32_t baseA, uint32_t baseB, int kOff,
                                         int m0, int n0, int lane,
                                         float c[2][8][4]) {
#pragma unroll
    for (int ks = 0; ks < 4; ks++) {
        uint32_t a[2][4];
#pragma unroll
        for (int mi = 0; mi < 2; mi++) {
            int row = m0 + mi * 16 + (lane & 15);
            int chunk = ks * 2 + (lane >> 4);
            int swz = chunk ^ (row & 7);
            ldsm_x4(baseA + row * 128 + swz * 16,
                    a[mi][0], a[mi][1], a[mi][2], a[mi][3]);
        }
        uint32_t b[4][4];
#pragma unroll
        for (int np = 0; np < 4; np++) {
            int row = kOff + ks * 16 + (lane & 15);
            int chunk = (n0 >> 3) + np * 2 + (lane >> 4);
            int swz = chunk ^ (row & 7);
            ldsm_x4_t(baseB + row * 256 + swz * 16,
                      b[np][0], b[np][1], b[np][2], b[np][3]);
        }
#pragma unroll
        for (int mi = 0; mi < 2; mi++)
#pragma unroll
            for (int ni = 0; ni < 8; ni++)
                mma16816(c[mi][ni], a[mi], &b[ni >> 1][(ni & 1) * 2]);
    }
}

__global__ __launch_bounds__(512)
void gemm_fused_kernel(const float* __restrict__ A,
                       const float* __restrict__ asi, const float* __restrict__ adi,
                       const float* __restrict__ aso, const float* __restrict__ ado,
                       int M) {
    extern __shared__ __align__(16) char dynsmem[];
    char* sW = dynsmem;                 // [mat][128 rows x 256 B]  = 64 KB
    char* sA = dynsmem + 65536;         // [buf][128 rows x 128 B]  = 32 KB

    int t = threadIdx.x;
    int w = t >> 5;
    int lane = t & 31;
    int mat = w >> 3;
    int w8 = w & 7;
    int m0 = (w8 >> 1) * 32;
    int n0 = (w8 & 1) * 64;
    int row0 = blockIdx.x * 128;

    uint32_t baseW = (uint32_t)__cvta_generic_to_shared(sW) + mat * 32768;
    uint32_t baseA0 = (uint32_t)__cvta_generic_to_shared(sA);
    uint32_t baseA1 = baseA0 + 16384;

    float c[2][8][4];
#pragma unroll
    for (int mi = 0; mi < 2; mi++)
#pragma unroll
        for (int ni = 0; ni < 8; ni++)
#pragma unroll
            for (int q = 0; q < 4; q++) c[mi][ni][q] = 0.f;

#pragma unroll
    for (int i = 0; i < 16; i++) {
        int idx = i * 512 + t;
        int m = idx >> 12;
        int r = (idx >> 5) & 127;
        int c4 = idx & 31;
        uint2 v = *(const uint2*)&g_W_h[m][r * DIM + c4 * 4];
        int swz = (c4 >> 1) ^ (r & 7);
        *(uint2*)(sW + m * 32768 + r * 256 + swz * 16 + (c4 & 1) * 8) = v;
    }
#pragma unroll
    for (int i = 0; i < 4; i++) {
        int idx = i * 512 + t;
        int row = idx >> 4;
        int c4 = idx & 15;
        float4 v = make_float4(0.f, 0.f, 0.f, 0.f);
        if (row0 + row < M)
            v = *(const float4*)&A[(size_t)(row0 + row) * DIM + c4 * 4];
        __half2 h0 = __floats2half2_rn(v.x, v.y);
        __half2 h1 = __floats2half2_rn(v.z, v.w);
        int swz = (c4 >> 1) ^ (row & 7);
        *(uint2*)(sA + row * 128 + swz * 16 + (c4 & 1) * 8) =
            make_uint2(*(unsigned*)&h0, *(unsigned*)&h1);
    }
    __syncthreads();

    float4 ra[4];
#pragma unroll
    for (int i = 0; i < 4; i++) {
        int idx = i * 512 + t;
        int row = idx >> 4;
        int c4 = idx & 15;
        ra[i] = make_float4(0.f, 0.f, 0.f, 0.f);
        if (row0 + row < M)
            ra[i] = *(const float4*)&A[(size_t)(row0 + row) * DIM + 64 + c4 * 4];
    }

    mma_tile(baseA0, baseW, 0, m0, n0, lane, c);

#pragma unroll
    for (int i = 0; i < 4; i++) {
        int idx = i * 512 + t;
        int row = idx >> 4;
        int c4 = idx & 15;
        __half2 h0 = __floats2half2_rn(ra[i].x, ra[i].y);
        __half2 h1 = __floats2half2_rn(ra[i].z, ra[i].w);
        int swz = (c4 >> 1) ^ (row & 7);
        *(uint2*)(sA + 16384 + row * 128 + swz * 16 + (c4 & 1) * 8) =
            make_uint2(*(unsigned*)&h0, *(unsigned*)&h1);
    }
    __syncthreads();

    mma_tile(baseA1, baseW, 64, m0, n0, lane, c);

    // ---- epilogue 1: fp16 h stores ----
    __half* Ch = mat ? g_h_out_h : g_h_in_h;
    int gid = lane >> 2;
    int qq = lane & 3;
#pragma unroll
    for (int mi = 0; mi < 2; mi++) {
#pragma unroll
        for (int ni = 0; ni < 8; ni++) {
            int row = row0 + m0 + mi * 16 + gid;
            int col = n0 + ni * 8 + qq * 2;
            if (row < M) {
                __half2 hv = __floats2half2_rn(c[mi][ni][0], c[mi][ni][1]);
                *(__half2*)&Ch[(size_t)row * DIM + col] = hv;
            }
            if (row + 8 < M) {
                __half2 hv = __floats2half2_rn(c[mi][ni][2], c[mi][ni][3]);
                *(__half2*)&Ch[(size_t)(row + 8) * DIM + col] = hv;
            }
        }
    }

    // ---- epilogue 2: alpha logits ----
    const float* av_s = mat ? aso : asi;
    const float* av_d = mat ? ado : adi;
    float* p_src = mat ? g_asrc_out : g_asrc_in;
    float* p_dst = mat ? g_adst_out : g_adst_in;
    int hb = (w8 & 1) * 4;

#pragma unroll
    for (int mi = 0; mi < 2; mi++) {
        float ps[2][4], pd[2][4];
#pragma unroll
        for (int r = 0; r < 2; r++)
#pragma unroll
            for (int hl = 0; hl < 4; hl++) { ps[r][hl] = 0.f; pd[r][hl] = 0.f; }
#pragma unroll
        for (int ni = 0; ni < 8; ni++) {
            int col = n0 + ni * 8 + qq * 2;
            float s0 = __ldg(&av_s[col]), s1 = __ldg(&av_s[col + 1]);
            float d0 = __ldg(&av_d[col]), d1 = __ldg(&av_d[col + 1]);
            int hl = ni >> 1;
            ps[0][hl] += c[mi][ni][0] * s0 + c[mi][ni][1] * s1;
            ps[1][hl] += c[mi][ni][2] * s0 + c[mi][ni][3] * s1;
            pd[0][hl] += c[mi][ni][0] * d0 + c[mi][ni][1] * d1;
            pd[1][hl] += c[mi][ni][2] * d0 + c[mi][ni][3] * d1;
        }
#pragma unroll
        for (int r = 0; r < 2; r++)
#pragma unroll
            for (int hl = 0; hl < 4; hl++) {
                ps[r][hl] += __shfl_xor_sync(0xFFFFFFFFu, ps[r][hl], 1);
                ps[r][hl] += __shfl_xor_sync(0xFFFFFFFFu, ps[r][hl], 2);
                pd[r][hl] += __shfl_xor_sync(0xFFFFFFFFu, pd[r][hl], 1);
                pd[r][hl] += __shfl_xor_sync(0xFFFFFFFFu, pd[r][hl], 2);
            }
        if (qq == 0) {
#pragma unroll
            for (int r = 0; r < 2; r++) {
                int row = row0 + m0 + mi * 16 + gid + r * 8;
                if (row < M) {
                    *(float4*)&p_src[row * HEADS + hb] =
                        make_float4(ps[r][0], ps[r][1], ps[r][2], ps[r][3]);
                    *(float4*)&p_dst[row * HEADS + hb] =
                        make_float4(pd[r][0], pd[r][1], pd[r][2], pd[r][3]);
                }
            }
        }
    }
}

// ---------------- aggregation: warp per node, 2-deep software pipeline ----------
__global__ __launch_bounds__(256)
void agg_kernel(float* __restrict__ out,
                const float* __restrict__ b_in,
                const float* __restrict__ b_out) {
    int w = (blockIdx.x * blockDim.x + threadIdx.x) >> 5;
    if (w >= NN) return;
    int n = w;
    int lane = threadIdx.x & 31;
    int c4 = lane * 4;
    int hd = lane >> 2;

    float4 bi = *(const float4*)&b_in[c4];
    float4 bo = *(const float4*)&b_out[c4];
    float o0 = bi.x + bo.x, o1 = bi.y + bo.y;
    float o2 = bi.z + bo.z, o3 = bi.w + bo.w;

#pragma unroll
    for (int dir = 0; dir < 2; dir++) {
        const float*  asrc = dir ? g_asrc_out : g_asrc_in;
        const float*  adst = dir ? g_adst_out : g_adst_in;
        const __half* hh   = dir ? g_h_out_h  : g_h_in_h;

        int base = g_off[dir * NN + n];
        int deg  = g_off[dir * NN + n + 1] - base;
        float adst_l = __ldg(&adst[n * HEADS + hd]);

        float den = 0.f;
        float a0 = 0.f, a1 = 0.f, a2 = 0.f, a3 = 0.f;

        int j = 0;
        for (; j + 2 <= deg; j += 2) {
            int s0 = __ldg(&g_nbr[base + j]);
            int s1 = __ldg(&g_nbr[base + j + 1]);
            float al0 = __ldg(&asrc[s0 * HEADS + hd]);
            float al1 = __ldg(&asrc[s1 * HEADS + hd]);
            uint2 v0 = *(const uint2*)&hh[(size_t)s0 * DIM + c4];
            uint2 v1 = *(const uint2*)&hh[(size_t)s1 * DIM + c4];

            float p0 = __expf(lrelu(al0 + adst_l));
            float p1 = __expf(lrelu(al1 + adst_l));

            float2 e0 = __half22float2(*reinterpret_cast<__half2*>(&v0.x));
            float2 e1 = __half22float2(*reinterpret_cast<__half2*>(&v0.y));
            float2 f0 = __half22float2(*reinterpret_cast<__half2*>(&v1.x));
            float2 f1 = __half22float2(*reinterpret_cast<__half2*>(&v1.y));

            den += p0 + p1;
            a0 += p0 * e0.x + p1 * f0.x;
            a1 += p0 * e0.y + p1 * f0.y;
            a2 += p0 * e1.x + p1 * f1.x;
            a3 += p0 * e1.y + p1 * f1.y;
        }
        if (j < deg) {
            int s = __ldg(&g_nbr[base + j]);
            float li = lrelu(__ldg(&asrc[s * HEADS + hd]) + adst_l);
            float p = __expf(li);
            uint2 v = *(const uint2*)&hh[(size_t)s * DIM + c4];
            float2 f0 = __half22float2(*reinterpret_cast<__half2*>(&v.x));
            float2 f1 = __half22float2(*reinterpret_cast<__half2*>(&v.y));
            den += p;
            a0 += p * f0.x;
            a1 += p * f0.y;
            a2 += p * f1.x;
            a3 += p * f1.y;
        }

        float r = (deg > 0) ? __frcp_rn(den) : 0.f;
        o0 += a0 * r;
        o1 += a1 * r;
        o2 += a2 * r;
        o3 += a3 * r;
    }

    *(float4*)&out[(size_t)n * DIM + c4] = make_float4(o0, o1, o2, o3);
}

// ---------------- launch --------------------------------------------------------
extern "C" void kernel_launch(void* const* d_in, const int* in_sizes, int n_in,
                              void* d_out, int out_size) {
    const float* x        = (const float*)d_in[0];
    const int*   ei       = (const int*)d_in[1];
    const float* W_in     = (const float*)d_in[2];
    const float* a_src_in = (const float*)d_in[3];
    const float* a_dst_in = (const float*)d_in[4];
    const float* b_in     = (const float*)d_in[5];
    const float* W_out    = (const float*)d_in[6];
    const float* a_src_out= (const float*)d_in[7];
    const float* a_dst_out= (const float*)d_in[8];
    const float* b_out    = (const float*)d_in[9];
    float* out = (float*)d_out;

    const int GEMM_SMEM = 65536 + 32768;   // 96 KB dynamic
    cudaFuncSetAttribute(gemm_fused_kernel,
                         cudaFuncAttributeMaxDynamicSharedMemorySize, GEMM_SMEM);

    static cudaStream_t s_side = nullptr;
    static cudaEvent_t ev_fork = nullptr, ev_join = nullptr;
    if (s_side == nullptr) {
        cudaStreamCreateWithFlags(&s_side, cudaStreamNonBlocking);
        cudaEventCreateWithFlags(&ev_fork, cudaEventDisableTiming);
        cudaEventCreateWithFlags(&ev_join, cudaEventDisableTiming);
    }

    // fork: CSR chain on side stream; wconv + GEMM on main stream
    cudaEventRecord(ev_fork, 0);
    cudaStreamWaitEvent(s_side, ev_fork, 0);

    zero_cnt_kernel<<<(NN2 + 255) / 256, 256, 0, s_side>>>();
    hist_kernel<<<(EE + 255) / 256, 256, 0, s_side>>>(ei);
    scan_fused_kernel<<<NB_SCAN, 256, 0, s_side>>>();
    scatter_kernel<<<(EE + 255) / 256, 256, 0, s_side>>>(ei);
    cudaEventRecord(ev_join, s_side);

    wconv_kernel<<<(2 * DIM * DIM / 4 + 255) / 256, 256>>>(W_in, W_out);
    gemm_fused_kernel<<<(NN + 127) / 128, 512, GEMM_SMEM>>>(
        x, a_src_in, a_dst_in, a_src_out, a_dst_out, NN);

    // join, then aggregate
    cudaStreamWaitEvent(0, ev_join, 0);
    agg_kernel<<<(NN * 32 + 255) / 256, 256>>>(out, b_in, b_out);
}